// round 12
// baseline (speedup 1.0000x reference)
#include <cuda_runtime.h>
#include <cuda_fp16.h>
#include <math.h>

#define BB 1024
#define TT 512
#define II 4
#define HH 32
#define GG 96   // 3*H

#define NC 8            // pipeline chunks
#define CH (BB / NC)    // batches per chunk

typedef unsigned long long u64;

// Scratch sequence buffers (allocation-free rule: __device__ globals).
__device__ __half g_h1 [(size_t)BB * TT * 2 * HH];   // layer0 out (fp16)
__device__ u64    g_xg [(size_t)2 * BB * TT * HH];   // layer1 gates packed (r,z,n,pad)
__device__ float  g_out[(size_t)BB * TT * 2 * HH];   // layer1 out (fp32)

__device__ __forceinline__ u64 fma2(u64 a, u64 b, u64 c) {
    u64 d;
    asm("fma.rn.f32x2 %0, %1, %2, %3;" : "=l"(d) : "l"(a), "l"(b), "l"(c));
    return d;
}
__device__ __forceinline__ float sum2(u64 v) {
    float lo, hi;
    asm("mov.b64 {%0, %1}, %2;" : "=f"(lo), "=f"(hi) : "l"(v));
    return lo + hi;
}
__device__ __forceinline__ u64 pack2(float lo, float hi) {
    u64 d;
    asm("mov.b64 %0, {%1, %2};" : "=l"(d) : "f"(lo), "f"(hi));
    return d;
}
__device__ __forceinline__ float frcp(float x) {
    float y;
    asm("rcp.approx.f32 %0, %1;" : "=f"(y) : "f"(x));
    return y;
}
__device__ __forceinline__ float fsig(float x) {
    return frcp(1.0f + __expf(-x));
}
__device__ __forceinline__ float ftanh(float x) {
    const float e = __expf(2.0f * x);
    return fmaf(-2.0f, frcp(e + 1.0f), 1.0f);
}
__device__ __forceinline__ __half2 u64_to_h2(u64 v) {
    float lo, hi;
    asm("mov.b64 {%0, %1}, %2;" : "=f"(lo), "=f"(hi) : "l"(v));
    return __floats2half2_rn(lo, hi);
}
__device__ __forceinline__ float h2sum(__half2 v) {
    return __low2float(v) + __high2float(v);
}
#define H2(u) (*(const __half2*)&(u))

// ---------------------------------------------------------------------------
// Layer 0: one warp per (b, dir). HFMA2 MACs, prefetch depth 2.
// grid: (CH/4, 2), block 128.
// ---------------------------------------------------------------------------
__global__ void __launch_bounds__(128) gru_l0(
    const float* __restrict__ x,
    const float* __restrict__ w_ih,
    const float* __restrict__ w_hh,
    const float* __restrict__ b_ih,
    const float* __restrict__ b_hh,
    int b0off)
{
    __shared__ __align__(16) __half sh[4][2][32];

    const int warp = threadIdx.x >> 5;
    const int j    = threadIdx.x & 31;
    const int dir  = blockIdx.y;
    const int b    = b0off + blockIdx.x * 4 + warp;

    const u64* w64 = (const u64*)w_hh;
    __half2 wr[16], wz[16], wn[16];
    {
        const int rb = (dir * GG + j) * 16;
        const int zb = (dir * GG + 32 + j) * 16;
        const int nb = (dir * GG + 64 + j) * 16;
        #pragma unroll
        for (int m = 0; m < 16; m++) {
            wr[m] = u64_to_h2(w64[rb + m]);
            wz[m] = u64_to_h2(w64[zb + m]);
            wn[m] = u64_to_h2(w64[nb + m]);
        }
    }
    const u64* wi64 = (const u64*)w_ih;
    const u64 wrA = wi64[(dir * GG + j) * 2],      wrB = wi64[(dir * GG + j) * 2 + 1];
    const u64 wzA = wi64[(dir * GG + 32 + j) * 2], wzB = wi64[(dir * GG + 32 + j) * 2 + 1];
    const u64 wnA = wi64[(dir * GG + 64 + j) * 2], wnB = wi64[(dir * GG + 64 + j) * 2 + 1];

    const u64 br2 = pack2(b_ih[dir * GG + j]      + b_hh[dir * GG + j],      0.0f);
    const u64 bz2 = pack2(b_ih[dir * GG + 32 + j] + b_hh[dir * GG + 32 + j], 0.0f);
    const u64 bx2 = pack2(b_ih[dir * GG + 64 + j], 0.0f);
    const float bhn = b_hh[dir * GG + 64 + j];

    float h = 0.0f;
    const int tstep = dir ? -1 : 1;
    int t = dir ? (TT - 1) : 0;

    const ulonglong2* xb2 = (const ulonglong2*)(x + (size_t)b * TT * II);
    __half* ob = g_h1 + (size_t)b * TT * 2 * HH + dir * HH + j;

    ulonglong2 xq0 = xb2[t];
    ulonglong2 xq1 = xb2[t + tstep];

    for (int s = 0; s < TT; ++s, t += tstep) {
        int tp = t + 2 * tstep;
        tp = (tp < 0) ? 0 : ((tp >= TT) ? (TT - 1) : tp);
        const ulonglong2 xq2 = xb2[tp];

        const int par = s & 1;
        sh[warp][par][j] = __float2half(h);
        __syncwarp();

        const u64 rin2 = fma2(wrA, xq0.x, fma2(wrB, xq0.y, br2));
        const u64 zin2 = fma2(wzA, xq0.x, fma2(wzB, xq0.y, bz2));
        const u64 xin2 = fma2(wnA, xq0.x, fma2(wnB, xq0.y, bx2));

        __half2 r0, r1, z0, z1, n0, n1;
        r0 = r1 = z0 = z1 = n0 = n1 = __floats2half2_rn(0.0f, 0.0f);
        const uint4* hv = (const uint4*)sh[warp][par];
        #pragma unroll
        for (int q = 0; q < 4; q++) {
            const uint4 u = hv[q];
            r0 = __hfma2(wr[4 * q],     H2(u.x), r0);
            z0 = __hfma2(wz[4 * q],     H2(u.x), z0);
            n0 = __hfma2(wn[4 * q],     H2(u.x), n0);
            r1 = __hfma2(wr[4 * q + 1], H2(u.y), r1);
            z1 = __hfma2(wz[4 * q + 1], H2(u.y), z1);
            n1 = __hfma2(wn[4 * q + 1], H2(u.y), n1);
            r0 = __hfma2(wr[4 * q + 2], H2(u.z), r0);
            z0 = __hfma2(wz[4 * q + 2], H2(u.z), z0);
            n0 = __hfma2(wn[4 * q + 2], H2(u.z), n0);
            r1 = __hfma2(wr[4 * q + 3], H2(u.w), r1);
            z1 = __hfma2(wz[4 * q + 3], H2(u.w), z1);
            n1 = __hfma2(wn[4 * q + 3], H2(u.w), n1);
        }

        const float r = fsig(sum2(rin2) + h2sum(__hadd2(r0, r1)));
        const float z = fsig(sum2(zin2) + h2sum(__hadd2(z0, z1)));
        const float n = ftanh(sum2(xin2) + r * (bhn + h2sum(__hadd2(n0, n1))));
        h = n + z * (h - n);

        ob[(size_t)t * 2 * HH] = __float2half(h);
        xq0 = xq1; xq1 = xq2;
    }
}

// ---------------------------------------------------------------------------
// Layer 1 input projection, packed u64 gate output. block 128, grid CH.
// ---------------------------------------------------------------------------
__global__ void __launch_bounds__(128) gru_l1_xg(
    const float* __restrict__ w_ih,
    const float* __restrict__ b_ih,
    int b0off)
{
    __shared__ __align__(16) unsigned int sx[4][2][2][32];

    const int w = threadIdx.x >> 5;
    const int j = threadIdx.x & 31;

    const int task  = blockIdx.x * 4 + w;   // (brel*2 + dir)*2 + chunkhalf
    const int chalf = task & 1;
    const int bd    = task >> 1;
    const int dir   = bd & 1;
    const int b     = b0off + (bd >> 1);

    const u64* w64 = (const u64*)w_ih;
    __half2 wgr[32], wgz[32], wgn[32];
    {
        const int rb = (dir * GG + j) * 32;
        const int zb = (dir * GG + 32 + j) * 32;
        const int nb = (dir * GG + 64 + j) * 32;
        #pragma unroll
        for (int m = 0; m < 32; m++) {
            wgr[m] = u64_to_h2(w64[rb + m]);
            wgz[m] = u64_to_h2(w64[zb + m]);
            wgn[m] = u64_to_h2(w64[nb + m]);
        }
    }
    const float br = b_ih[dir * GG + j];
    const float bz = b_ih[dir * GG + 32 + j];
    const float bn = b_ih[dir * GG + 64 + j];

    const unsigned int* ib = (const unsigned int*)g_h1 + (size_t)b * TT * 32;
    u64* xo = g_xg + ((size_t)(dir * BB + b) * TT) * 32 + j;

    const int t0 = chalf * (TT / 2);
    unsigned int a0 = ib[(size_t)t0 * 32 + j];
    unsigned int a1 = ib[(size_t)(t0 + 1) * 32 + j];

    for (int s = 0; s < TT / 4; ++s) {
        const int t  = t0 + 2 * s;
        const int tn = (s == TT / 4 - 1) ? t : (t + 2);
        const unsigned int p0 = ib[(size_t)tn * 32 + j];
        const unsigned int p1 = ib[(size_t)(tn + 1) * 32 + j];

        const int par = s & 1;
        sx[w][par][0][j] = a0;
        sx[w][par][1][j] = a1;
        __syncwarp();

        __half2 R0, R1, Z0, Z1, N0, N1;
        __half2 R2, R3, Z2, Z3, N2, N3;
        R0 = R1 = Z0 = Z1 = N0 = N1 = __floats2half2_rn(0.0f, 0.0f);
        R2 = R3 = Z2 = Z3 = N2 = N3 = __floats2half2_rn(0.0f, 0.0f);

        const uint4* r0p = (const uint4*)&sx[w][par][0][0];
        const uint4* r1p = (const uint4*)&sx[w][par][1][0];
        #pragma unroll
        for (int q = 0; q < 8; q++) {
            const uint4 u = r0p[q];
            const uint4 v = r1p[q];
            R0 = __hfma2(wgr[4 * q],     H2(u.x), R0);
            Z0 = __hfma2(wgz[4 * q],     H2(u.x), Z0);
            N0 = __hfma2(wgn[4 * q],     H2(u.x), N0);
            R1 = __hfma2(wgr[4 * q + 1], H2(u.y), R1);
            Z1 = __hfma2(wgz[4 * q + 1], H2(u.y), Z1);
            N1 = __hfma2(wgn[4 * q + 1], H2(u.y), N1);
            R0 = __hfma2(wgr[4 * q + 2], H2(u.z), R0);
            Z0 = __hfma2(wgz[4 * q + 2], H2(u.z), Z0);
            N0 = __hfma2(wgn[4 * q + 2], H2(u.z), N0);
            R1 = __hfma2(wgr[4 * q + 3], H2(u.w), R1);
            Z1 = __hfma2(wgz[4 * q + 3], H2(u.w), Z1);
            N1 = __hfma2(wgn[4 * q + 3], H2(u.w), N1);

            R2 = __hfma2(wgr[4 * q],     H2(v.x), R2);
            Z2 = __hfma2(wgz[4 * q],     H2(v.x), Z2);
            N2 = __hfma2(wgn[4 * q],     H2(v.x), N2);
            R3 = __hfma2(wgr[4 * q + 1], H2(v.y), R3);
            Z3 = __hfma2(wgz[4 * q + 1], H2(v.y), Z3);
            N3 = __hfma2(wgn[4 * q + 1], H2(v.y), N3);
            R2 = __hfma2(wgr[4 * q + 2], H2(v.z), R2);
            Z2 = __hfma2(wgz[4 * q + 2], H2(v.z), Z2);
            N2 = __hfma2(wgn[4 * q + 2], H2(v.z), N2);
            R3 = __hfma2(wgr[4 * q + 3], H2(v.w), R3);
            Z3 = __hfma2(wgz[4 * q + 3], H2(v.w), Z3);
            N3 = __hfma2(wgn[4 * q + 3], H2(v.w), N3);
        }

        {
            const float rv = br + h2sum(__hadd2(R0, R1));
            const float zv = bz + h2sum(__hadd2(Z0, Z1));
            const float nv = bn + h2sum(__hadd2(N0, N1));
            const __half2 lo = __floats2half2_rn(rv, zv);
            const __half2 hi = __floats2half2_rn(nv, 0.0f);
            u64 pk;
            asm("mov.b64 %0, {%1, %2};" : "=l"(pk)
                : "r"(*(const unsigned int*)&lo), "r"(*(const unsigned int*)&hi));
            xo[(size_t)t * 32] = pk;
        }
        {
            const float rv = br + h2sum(__hadd2(R2, R3));
            const float zv = bz + h2sum(__hadd2(Z2, Z3));
            const float nv = bn + h2sum(__hadd2(N2, N3));
            const __half2 lo = __floats2half2_rn(rv, zv);
            const __half2 hi = __floats2half2_rn(nv, 0.0f);
            u64 pk;
            asm("mov.b64 %0, {%1, %2};" : "=l"(pk)
                : "r"(*(const unsigned int*)&lo), "r"(*(const unsigned int*)&hi));
            xo[(size_t)(t + 1) * 32] = pk;
        }
        a0 = p0; a1 = p1;
    }
}

// ---------------------------------------------------------------------------
// Layer 1 recurrence: single u64 gate load/step, prefetch depth 3.
// grid (CH/4, 2), block 128.
// ---------------------------------------------------------------------------
__global__ void __launch_bounds__(128) gru_l1_rec(
    const float* __restrict__ w_hh,
    const float* __restrict__ b_hh,
    int b0off)
{
    __shared__ __align__(16) __half sh[4][2][32];

    const int warp = threadIdx.x >> 5;
    const int j    = threadIdx.x & 31;
    const int dir  = blockIdx.y;
    const int b    = b0off + blockIdx.x * 4 + warp;

    const u64* w64 = (const u64*)w_hh;
    __half2 wr[16], wz[16], wn[16];
    {
        const int rb = (dir * GG + j) * 16;
        const int zb = (dir * GG + 32 + j) * 16;
        const int nb = (dir * GG + 64 + j) * 16;
        #pragma unroll
        for (int m = 0; m < 16; m++) {
            wr[m] = u64_to_h2(w64[rb + m]);
            wz[m] = u64_to_h2(w64[zb + m]);
            wn[m] = u64_to_h2(w64[nb + m]);
        }
    }
    const float brh = b_hh[dir * GG + j];
    const float bzh = b_hh[dir * GG + 32 + j];
    const float bhn = b_hh[dir * GG + 64 + j];

    float h = 0.0f;
    const int tstep = dir ? -1 : 1;
    int t = dir ? (TT - 1) : 0;

    const u64* xgb = g_xg + ((size_t)(dir * BB + b) * TT) * 32 + j;
    float* ob = g_out + (size_t)b * TT * 2 * HH + dir * HH + j;

    u64 q0 = xgb[(size_t)t * 32];
    u64 q1 = xgb[(size_t)(t + tstep) * 32];
    u64 q2 = xgb[(size_t)(t + 2 * tstep) * 32];

    for (int s = 0; s < TT; ++s, t += tstep) {
        int tp = t + 3 * tstep;
        tp = (tp < 0) ? 0 : ((tp >= TT) ? (TT - 1) : tp);
        const u64 q3 = xgb[(size_t)tp * 32];

        const int par = s & 1;
        sh[warp][par][j] = __float2half(h);
        __syncwarp();

        unsigned int lo_u, hi_u;
        asm("mov.b64 {%0, %1}, %2;" : "=r"(lo_u), "=r"(hi_u) : "l"(q0));
        const __half2 lo = H2(lo_u);
        const __half2 hi = H2(hi_u);
        const float xr = __low2float(lo);
        const float xz = __high2float(lo);
        const float xn = __low2float(hi);

        __half2 r0, r1, z0, z1, n0, n1;
        r0 = r1 = z0 = z1 = n0 = n1 = __floats2half2_rn(0.0f, 0.0f);
        const uint4* hv = (const uint4*)sh[warp][par];
        #pragma unroll
        for (int q = 0; q < 4; q++) {
            const uint4 u = hv[q];
            r0 = __hfma2(wr[4 * q],     H2(u.x), r0);
            z0 = __hfma2(wz[4 * q],     H2(u.x), z0);
            n0 = __hfma2(wn[4 * q],     H2(u.x), n0);
            r1 = __hfma2(wr[4 * q + 1], H2(u.y), r1);
            z1 = __hfma2(wz[4 * q + 1], H2(u.y), z1);
            n1 = __hfma2(wn[4 * q + 1], H2(u.y), n1);
            r0 = __hfma2(wr[4 * q + 2], H2(u.z), r0);
            z0 = __hfma2(wz[4 * q + 2], H2(u.z), z0);
            n0 = __hfma2(wn[4 * q + 2], H2(u.z), n0);
            r1 = __hfma2(wr[4 * q + 3], H2(u.w), r1);
            z1 = __hfma2(wz[4 * q + 3], H2(u.w), z1);
            n1 = __hfma2(wn[4 * q + 3], H2(u.w), n1);
        }

        const float r = fsig(xr + brh + h2sum(__hadd2(r0, r1)));
        const float z = fsig(xz + bzh + h2sum(__hadd2(z0, z1)));
        const float n = ftanh(xn + r * (bhn + h2sum(__hadd2(n0, n1))));
        h = n + z * (h - n);

        ob[(size_t)t * 2 * HH] = h;
        q0 = q1; q1 = q2; q2 = q3;
    }
}

// ---------------------------------------------------------------------------
// Epilogue: single-pass online-softmax attention pooling + sigmoid FC.
// ---------------------------------------------------------------------------
__global__ void __launch_bounds__(256) attn_fc_kernel(
    const float* __restrict__ attn_w,
    const float* __restrict__ fc_w,
    const float* __restrict__ fc_b,
    float* __restrict__ y,
    int b0off)
{
    __shared__ float saw[64], sfw[64];
    __shared__ float sm[8], sz[8];
    __shared__ float sctx[8][64];

    const int b    = b0off + blockIdx.x;
    const int tid  = threadIdx.x;
    const int warp = tid >> 5;
    const int lane = tid & 31;

    if (tid < 64) {
        saw[tid] = attn_w[tid];
        sfw[tid] = fc_w[tid];
    }
    __syncthreads();

    const float aw0 = saw[lane], aw1 = saw[lane + 32];
    const float* ob = g_out + (size_t)b * TT * 64;

    float m = -INFINITY, Z = 0.0f, c0 = 0.0f, c1 = 0.0f;
    for (int t = warp; t < TT; t += 8) {
        const float* p = ob + (size_t)t * 64;
        const float q0 = p[lane];
        const float q1 = p[lane + 32];
        float v = q0 * aw0 + q1 * aw1;
        #pragma unroll
        for (int o = 16; o; o >>= 1) v += __shfl_xor_sync(0xffffffffu, v, o);
        const float mn = fmaxf(m, v);
        const float sc = __expf(m - mn);
        const float e  = __expf(v - mn);
        Z  = Z * sc + e;
        c0 = c0 * sc + e * q0;
        c1 = c1 * sc + e * q1;
        m = mn;
    }
    if (lane == 0) sm[warp] = m;
    __syncthreads();

    float M = sm[0];
    #pragma unroll
    for (int w = 1; w < 8; w++) M = fmaxf(M, sm[w]);
    const float sc = __expf(m - M);
    if (lane == 0) sz[warp] = Z * sc;
    sctx[warp][lane]      = c0 * sc;
    sctx[warp][lane + 32] = c1 * sc;
    __syncthreads();

    if (tid < 32) {
        float Zt = 0.0f, C0 = 0.0f, C1 = 0.0f;
        #pragma unroll
        for (int w = 0; w < 8; w++) {
            Zt += sz[w];
            C0 += sctx[w][lane];
            C1 += sctx[w][lane + 32];
        }
        float v = C0 * sfw[lane] + C1 * sfw[lane + 32];
        #pragma unroll
        for (int o = 16; o; o >>= 1) v += __shfl_xor_sync(0xffffffffu, v, o);
        if (lane == 0) {
            y[b] = frcp(1.0f + __expf(-(__fdividef(v, Zt) + fc_b[0])));
        }
    }
}

// ---------------------------------------------------------------------------
// Pipeline plumbing: streams/events created at program load (before the
// harness's memory baseline; never during capture). No device allocations.
// ---------------------------------------------------------------------------
static cudaStream_t g_s1, g_s2;
static cudaEvent_t  g_evFork;
static cudaEvent_t  g_evL0[NC], g_evXG[NC], g_evA[NC];
static struct PipeInit {
    PipeInit() {
        cudaStreamCreateWithFlags(&g_s1, cudaStreamNonBlocking);
        cudaStreamCreateWithFlags(&g_s2, cudaStreamNonBlocking);
        cudaEventCreateWithFlags(&g_evFork, cudaEventDisableTiming);
        for (int i = 0; i < NC; i++) {
            cudaEventCreateWithFlags(&g_evL0[i], cudaEventDisableTiming);
            cudaEventCreateWithFlags(&g_evXG[i], cudaEventDisableTiming);
            cudaEventCreateWithFlags(&g_evA[i],  cudaEventDisableTiming);
        }
    }
} g_pipe_init;

extern "C" void kernel_launch(void* const* d_in, const int* in_sizes, int n_in,
                              void* d_out, int out_size) {
    const float* x       = (const float*)d_in[0];
    const float* w_ih_l0 = (const float*)d_in[1];
    const float* w_hh_l0 = (const float*)d_in[2];
    const float* b_ih_l0 = (const float*)d_in[3];
    const float* b_hh_l0 = (const float*)d_in[4];
    const float* w_ih_l1 = (const float*)d_in[5];
    const float* w_hh_l1 = (const float*)d_in[6];
    const float* b_ih_l1 = (const float*)d_in[7];
    const float* b_hh_l1 = (const float*)d_in[8];
    const float* attn_w  = (const float*)d_in[9];
    // d_in[10] = attn_b (cancels in softmax)
    const float* fc_w    = (const float*)d_in[11];
    const float* fc_b    = (const float*)d_in[12];
    float* y = (float*)d_out;

    // fork side streams off the launch stream
    cudaEventRecord(g_evFork, 0);
    cudaStreamWaitEvent(g_s1, g_evFork, 0);
    cudaStreamWaitEvent(g_s2, g_evFork, 0);

    for (int c = 0; c < NC; c++) {
        const int b0 = c * CH;

        // stage 1: layer0 recurrence (stream 0)
        gru_l0<<<dim3(CH / 4, 2), 128, 0, 0>>>(
            x, w_ih_l0, w_hh_l0, b_ih_l0, b_hh_l0, b0);
        cudaEventRecord(g_evL0[c], 0);

        // stage 2: layer1 input projection (stream 1)
        cudaStreamWaitEvent(g_s1, g_evL0[c], 0);
        gru_l1_xg<<<CH, 128, 0, g_s1>>>(w_ih_l1, b_ih_l1, b0);
        cudaEventRecord(g_evXG[c], g_s1);

        // stage 3+4: layer1 recurrence + attention (stream 2)
        cudaStreamWaitEvent(g_s2, g_evXG[c], 0);
        gru_l1_rec<<<dim3(CH / 4, 2), 128, 0, g_s2>>>(w_hh_l1, b_hh_l1, b0);
        attn_fc_kernel<<<CH, 256, 0, g_s2>>>(attn_w, fc_w, fc_b, y, b0);
        cudaEventRecord(g_evA[c], g_s2);
    }

    // join everything back to the launch stream
    for (int c = 0; c < NC; c++) {
        cudaStreamWaitEvent(0, g_evA[c], 0);
    }
}

// round 13
// speedup vs baseline: 2.0714x; 2.0714x over previous
#include <cuda_runtime.h>
#include <cuda_fp16.h>
#include <math.h>

#define BB 1024
#define TT 512
#define II 4
#define HH 32
#define GG 96   // 3*H

typedef unsigned long long u64;

// Scratch sequence buffers (allocation-free rule: __device__ globals).
__device__ __half g_h1 [(size_t)BB * TT * 2 * HH];   // layer0 out (fp16)
__device__ u64    g_xg [(size_t)2 * BB * TT * HH];   // layer1 gates packed (r,z,n,pad)
__device__ float  g_out[(size_t)BB * TT * 2 * HH];   // layer1 out (fp32)

__device__ __forceinline__ u64 fma2(u64 a, u64 b, u64 c) {
    u64 d;
    asm("fma.rn.f32x2 %0, %1, %2, %3;" : "=l"(d) : "l"(a), "l"(b), "l"(c));
    return d;
}
__device__ __forceinline__ float sum2(u64 v) {
    float lo, hi;
    asm("mov.b64 {%0, %1}, %2;" : "=f"(lo), "=f"(hi) : "l"(v));
    return lo + hi;
}
__device__ __forceinline__ u64 pack2(float lo, float hi) {
    u64 d;
    asm("mov.b64 %0, {%1, %2};" : "=l"(d) : "f"(lo), "f"(hi));
    return d;
}
__device__ __forceinline__ float frcp(float x) {
    float y;
    asm("rcp.approx.f32 %0, %1;" : "=f"(y) : "f"(x));
    return y;
}
__device__ __forceinline__ float fsig(float x) {
    return frcp(1.0f + __expf(-x));
}
__device__ __forceinline__ float ftanh(float x) {
    const float e = __expf(2.0f * x);
    return fmaf(-2.0f, frcp(e + 1.0f), 1.0f);
}
__device__ __forceinline__ __half2 u64_to_h2(u64 v) {
    float lo, hi;
    asm("mov.b64 {%0, %1}, %2;" : "=f"(lo), "=f"(hi) : "l"(v));
    return __floats2half2_rn(lo, hi);
}
__device__ __forceinline__ float h2sum(__half2 v) {
    return __low2float(v) + __high2float(v);
}
#define H2(u) (*(const __half2*)&(u))

// ---------------------------------------------------------------------------
// Layer 0: one warp per (b, dir). HFMA2 MACs, prefetch depth 2.
// grid: (B/4, 2), block 128.
// ---------------------------------------------------------------------------
__global__ void __launch_bounds__(128) gru_l0(
    const float* __restrict__ x,      // [B,T,4]
    const float* __restrict__ w_ih,   // [2,96,4]
    const float* __restrict__ w_hh,   // [2,96,32]
    const float* __restrict__ b_ih,   // [2,96]
    const float* __restrict__ b_hh)   // [2,96]
{
    __shared__ __align__(16) __half sh[4][2][32];

    const int warp = threadIdx.x >> 5;
    const int j    = threadIdx.x & 31;
    const int dir  = blockIdx.y;
    const int b    = blockIdx.x * 4 + warp;

    const u64* w64 = (const u64*)w_hh;
    __half2 wr[16], wz[16], wn[16];
    {
        const int rb = (dir * GG + j) * 16;
        const int zb = (dir * GG + 32 + j) * 16;
        const int nb = (dir * GG + 64 + j) * 16;
        #pragma unroll
        for (int m = 0; m < 16; m++) {
            wr[m] = u64_to_h2(w64[rb + m]);
            wz[m] = u64_to_h2(w64[zb + m]);
            wn[m] = u64_to_h2(w64[nb + m]);
        }
    }
    const u64* wi64 = (const u64*)w_ih;
    const u64 wrA = wi64[(dir * GG + j) * 2],      wrB = wi64[(dir * GG + j) * 2 + 1];
    const u64 wzA = wi64[(dir * GG + 32 + j) * 2], wzB = wi64[(dir * GG + 32 + j) * 2 + 1];
    const u64 wnA = wi64[(dir * GG + 64 + j) * 2], wnB = wi64[(dir * GG + 64 + j) * 2 + 1];

    const u64 br2 = pack2(b_ih[dir * GG + j]      + b_hh[dir * GG + j],      0.0f);
    const u64 bz2 = pack2(b_ih[dir * GG + 32 + j] + b_hh[dir * GG + 32 + j], 0.0f);
    const u64 bx2 = pack2(b_ih[dir * GG + 64 + j], 0.0f);
    const float bhn = b_hh[dir * GG + 64 + j];

    float h = 0.0f;
    const int tstep = dir ? -1 : 1;
    int t = dir ? (TT - 1) : 0;

    const ulonglong2* xb2 = (const ulonglong2*)(x + (size_t)b * TT * II);
    __half* ob = g_h1 + (size_t)b * TT * 2 * HH + dir * HH + j;

    ulonglong2 xq0 = xb2[t];
    ulonglong2 xq1 = xb2[t + tstep];

    for (int s = 0; s < TT; ++s, t += tstep) {
        int tp = t + 2 * tstep;
        tp = (tp < 0) ? 0 : ((tp >= TT) ? (TT - 1) : tp);
        const ulonglong2 xq2 = xb2[tp];

        const int par = s & 1;
        sh[warp][par][j] = __float2half(h);
        __syncwarp();

        const u64 rin2 = fma2(wrA, xq0.x, fma2(wrB, xq0.y, br2));
        const u64 zin2 = fma2(wzA, xq0.x, fma2(wzB, xq0.y, bz2));
        const u64 xin2 = fma2(wnA, xq0.x, fma2(wnB, xq0.y, bx2));

        __half2 r0, r1, z0, z1, n0, n1;
        r0 = r1 = z0 = z1 = n0 = n1 = __floats2half2_rn(0.0f, 0.0f);
        const uint4* hv = (const uint4*)sh[warp][par];
        #pragma unroll
        for (int q = 0; q < 4; q++) {
            const uint4 u = hv[q];
            r0 = __hfma2(wr[4 * q],     H2(u.x), r0);
            z0 = __hfma2(wz[4 * q],     H2(u.x), z0);
            n0 = __hfma2(wn[4 * q],     H2(u.x), n0);
            r1 = __hfma2(wr[4 * q + 1], H2(u.y), r1);
            z1 = __hfma2(wz[4 * q + 1], H2(u.y), z1);
            n1 = __hfma2(wn[4 * q + 1], H2(u.y), n1);
            r0 = __hfma2(wr[4 * q + 2], H2(u.z), r0);
            z0 = __hfma2(wz[4 * q + 2], H2(u.z), z0);
            n0 = __hfma2(wn[4 * q + 2], H2(u.z), n0);
            r1 = __hfma2(wr[4 * q + 3], H2(u.w), r1);
            z1 = __hfma2(wz[4 * q + 3], H2(u.w), z1);
            n1 = __hfma2(wn[4 * q + 3], H2(u.w), n1);
        }

        const float r = fsig(sum2(rin2) + h2sum(__hadd2(r0, r1)));
        const float z = fsig(sum2(zin2) + h2sum(__hadd2(z0, z1)));
        const float n = ftanh(sum2(xin2) + r * (bhn + h2sum(__hadd2(n0, n1))));
        h = n + z * (h - n);

        ob[(size_t)t * 2 * HH] = __float2half(h);
        xq0 = xq1; xq1 = xq2;
    }
}

// ---------------------------------------------------------------------------
// Layer 1 input projection, packed u64 gate output. block 128, grid 1024.
// ---------------------------------------------------------------------------
__global__ void __launch_bounds__(128) gru_l1_xg(
    const float* __restrict__ w_ih,   // [2,96,64]
    const float* __restrict__ b_ih)   // [2,96]
{
    __shared__ __align__(16) unsigned int sx[4][2][2][32];

    const int w = threadIdx.x >> 5;
    const int j = threadIdx.x & 31;

    const int task  = blockIdx.x * 4 + w;   // (b*2 + dir)*2 + chunkhalf
    const int chalf = task & 1;
    const int bd    = task >> 1;
    const int dir   = bd & 1;
    const int b     = bd >> 1;

    const u64* w64 = (const u64*)w_ih;
    __half2 wgr[32], wgz[32], wgn[32];
    {
        const int rb = (dir * GG + j) * 32;
        const int zb = (dir * GG + 32 + j) * 32;
        const int nb = (dir * GG + 64 + j) * 32;
        #pragma unroll
        for (int m = 0; m < 32; m++) {
            wgr[m] = u64_to_h2(w64[rb + m]);
            wgz[m] = u64_to_h2(w64[zb + m]);
            wgn[m] = u64_to_h2(w64[nb + m]);
        }
    }
    const float br = b_ih[dir * GG + j];
    const float bz = b_ih[dir * GG + 32 + j];
    const float bn = b_ih[dir * GG + 64 + j];

    const unsigned int* ib = (const unsigned int*)g_h1 + (size_t)b * TT * 32;
    u64* xo = g_xg + ((size_t)(dir * BB + b) * TT) * 32 + j;

    const int t0 = chalf * (TT / 2);
    unsigned int a0 = ib[(size_t)t0 * 32 + j];
    unsigned int a1 = ib[(size_t)(t0 + 1) * 32 + j];

    for (int s = 0; s < TT / 4; ++s) {
        const int t  = t0 + 2 * s;
        const int tn = (s == TT / 4 - 1) ? t : (t + 2);
        const unsigned int p0 = ib[(size_t)tn * 32 + j];
        const unsigned int p1 = ib[(size_t)(tn + 1) * 32 + j];

        const int par = s & 1;
        sx[w][par][0][j] = a0;
        sx[w][par][1][j] = a1;
        __syncwarp();

        __half2 R0, R1, Z0, Z1, N0, N1;
        __half2 R2, R3, Z2, Z3, N2, N3;
        R0 = R1 = Z0 = Z1 = N0 = N1 = __floats2half2_rn(0.0f, 0.0f);
        R2 = R3 = Z2 = Z3 = N2 = N3 = __floats2half2_rn(0.0f, 0.0f);

        const uint4* r0p = (const uint4*)&sx[w][par][0][0];
        const uint4* r1p = (const uint4*)&sx[w][par][1][0];
        #pragma unroll
        for (int q = 0; q < 8; q++) {
            const uint4 u = r0p[q];
            const uint4 v = r1p[q];
            R0 = __hfma2(wgr[4 * q],     H2(u.x), R0);
            Z0 = __hfma2(wgz[4 * q],     H2(u.x), Z0);
            N0 = __hfma2(wgn[4 * q],     H2(u.x), N0);
            R1 = __hfma2(wgr[4 * q + 1], H2(u.y), R1);
            Z1 = __hfma2(wgz[4 * q + 1], H2(u.y), Z1);
            N1 = __hfma2(wgn[4 * q + 1], H2(u.y), N1);
            R0 = __hfma2(wgr[4 * q + 2], H2(u.z), R0);
            Z0 = __hfma2(wgz[4 * q + 2], H2(u.z), Z0);
            N0 = __hfma2(wgn[4 * q + 2], H2(u.z), N0);
            R1 = __hfma2(wgr[4 * q + 3], H2(u.w), R1);
            Z1 = __hfma2(wgz[4 * q + 3], H2(u.w), Z1);
            N1 = __hfma2(wgn[4 * q + 3], H2(u.w), N1);

            R2 = __hfma2(wgr[4 * q],     H2(v.x), R2);
            Z2 = __hfma2(wgz[4 * q],     H2(v.x), Z2);
            N2 = __hfma2(wgn[4 * q],     H2(v.x), N2);
            R3 = __hfma2(wgr[4 * q + 1], H2(v.y), R3);
            Z3 = __hfma2(wgz[4 * q + 1], H2(v.y), Z3);
            N3 = __hfma2(wgn[4 * q + 1], H2(v.y), N3);
            R2 = __hfma2(wgr[4 * q + 2], H2(v.z), R2);
            Z2 = __hfma2(wgz[4 * q + 2], H2(v.z), Z2);
            N2 = __hfma2(wgn[4 * q + 2], H2(v.z), N2);
            R3 = __hfma2(wgr[4 * q + 3], H2(v.w), R3);
            Z3 = __hfma2(wgz[4 * q + 3], H2(v.w), Z3);
            N3 = __hfma2(wgn[4 * q + 3], H2(v.w), N3);
        }

        {
            const float rv = br + h2sum(__hadd2(R0, R1));
            const float zv = bz + h2sum(__hadd2(Z0, Z1));
            const float nv = bn + h2sum(__hadd2(N0, N1));
            const __half2 lo = __floats2half2_rn(rv, zv);
            const __half2 hi = __floats2half2_rn(nv, 0.0f);
            u64 pk;
            asm("mov.b64 %0, {%1, %2};" : "=l"(pk)
                : "r"(*(const unsigned int*)&lo), "r"(*(const unsigned int*)&hi));
            xo[(size_t)t * 32] = pk;
        }
        {
            const float rv = br + h2sum(__hadd2(R2, R3));
            const float zv = bz + h2sum(__hadd2(Z2, Z3));
            const float nv = bn + h2sum(__hadd2(N2, N3));
            const __half2 lo = __floats2half2_rn(rv, zv);
            const __half2 hi = __floats2half2_rn(nv, 0.0f);
            u64 pk;
            asm("mov.b64 %0, {%1, %2};" : "=l"(pk)
                : "r"(*(const unsigned int*)&lo), "r"(*(const unsigned int*)&hi));
            xo[(size_t)(t + 1) * 32] = pk;
        }
        a0 = p0; a1 = p1;
    }
}

// ---------------------------------------------------------------------------
// Layer 1 recurrence FUSED with attention epilogue.
// Block = 8 warps = 4 batches x 2 dirs. After the T loop the same block pools
// its own 4 batches (2 warps per batch, online softmax) and writes y.
// grid (B/4), block 256.
// ---------------------------------------------------------------------------
__global__ void __launch_bounds__(256) gru_l1_rec_attn(
    const float* __restrict__ w_hh,   // [2,96,32]
    const float* __restrict__ b_hh,   // [2,96]
    const float* __restrict__ attn_w, // [1,64]
    const float* __restrict__ fc_w,   // [1,64]
    const float* __restrict__ fc_b,   // [1]
    float* __restrict__ y)            // [B,1]
{
    __shared__ __align__(16) __half sh[8][2][32];
    __shared__ float saw[64], sfw[64];
    __shared__ float sm[8], szs[8];
    __shared__ float sctx[8][64];

    const int warp = threadIdx.x >> 5;   // 0..7
    const int j    = threadIdx.x & 31;
    const int dir  = warp & 1;
    const int b    = blockIdx.x * 4 + (warp >> 1);

    if (threadIdx.x < 64) {
        saw[threadIdx.x] = attn_w[threadIdx.x];
        sfw[threadIdx.x] = fc_w[threadIdx.x];
    }

    const u64* w64 = (const u64*)w_hh;
    __half2 wr[16], wz[16], wn[16];
    {
        const int rb = (dir * GG + j) * 16;
        const int zb = (dir * GG + 32 + j) * 16;
        const int nb = (dir * GG + 64 + j) * 16;
        #pragma unroll
        for (int m = 0; m < 16; m++) {
            wr[m] = u64_to_h2(w64[rb + m]);
            wz[m] = u64_to_h2(w64[zb + m]);
            wn[m] = u64_to_h2(w64[nb + m]);
        }
    }
    const float brh = b_hh[dir * GG + j];
    const float bzh = b_hh[dir * GG + 32 + j];
    const float bhn = b_hh[dir * GG + 64 + j];

    float h = 0.0f;
    const int tstep = dir ? -1 : 1;
    int t = dir ? (TT - 1) : 0;

    const u64* xgb = g_xg + ((size_t)(dir * BB + b) * TT) * 32 + j;
    float* ob = g_out + (size_t)b * TT * 2 * HH + dir * HH + j;

    u64 q0 = xgb[(size_t)t * 32];
    u64 q1 = xgb[(size_t)(t + tstep) * 32];
    u64 q2 = xgb[(size_t)(t + 2 * tstep) * 32];

    for (int s = 0; s < TT; ++s, t += tstep) {
        int tp = t + 3 * tstep;
        tp = (tp < 0) ? 0 : ((tp >= TT) ? (TT - 1) : tp);
        const u64 q3 = xgb[(size_t)tp * 32];

        const int par = s & 1;
        sh[warp][par][j] = __float2half(h);
        __syncwarp();

        unsigned int lo_u, hi_u;
        asm("mov.b64 {%0, %1}, %2;" : "=r"(lo_u), "=r"(hi_u) : "l"(q0));
        const __half2 lo = H2(lo_u);
        const __half2 hi = H2(hi_u);
        const float xr = __low2float(lo);
        const float xz = __high2float(lo);
        const float xn = __low2float(hi);

        __half2 r0, r1, z0, z1, n0, n1;
        r0 = r1 = z0 = z1 = n0 = n1 = __floats2half2_rn(0.0f, 0.0f);
        const uint4* hv = (const uint4*)sh[warp][par];
        #pragma unroll
        for (int q = 0; q < 4; q++) {
            const uint4 u = hv[q];
            r0 = __hfma2(wr[4 * q],     H2(u.x), r0);
            z0 = __hfma2(wz[4 * q],     H2(u.x), z0);
            n0 = __hfma2(wn[4 * q],     H2(u.x), n0);
            r1 = __hfma2(wr[4 * q + 1], H2(u.y), r1);
            z1 = __hfma2(wz[4 * q + 1], H2(u.y), z1);
            n1 = __hfma2(wn[4 * q + 1], H2(u.y), n1);
            r0 = __hfma2(wr[4 * q + 2], H2(u.z), r0);
            z0 = __hfma2(wz[4 * q + 2], H2(u.z), z0);
            n0 = __hfma2(wn[4 * q + 2], H2(u.z), n0);
            r1 = __hfma2(wr[4 * q + 3], H2(u.w), r1);
            z1 = __hfma2(wz[4 * q + 3], H2(u.w), z1);
            n1 = __hfma2(wn[4 * q + 3], H2(u.w), n1);
        }

        const float r = fsig(xr + brh + h2sum(__hadd2(r0, r1)));
        const float z = fsig(xz + bzh + h2sum(__hadd2(z0, z1)));
        const float n = ftanh(xn + r * (bhn + h2sum(__hadd2(n0, n1))));
        h = n + z * (h - n);

        ob[(size_t)t * 2 * HH] = h;
        q0 = q1; q1 = q2; q2 = q3;
    }

    // ---- attention epilogue: 2 warps per batch, online softmax over T ----
    __syncthreads();

    const int ba   = blockIdx.x * 4 + (warp >> 1);   // this warp's batch
    const int half = warp & 1;                       // which half of t's

    const float aw0 = saw[j], aw1 = saw[j + 32];
    const float* obase = g_out + (size_t)ba * TT * 64;

    float m = -INFINITY, Z = 0.0f, c0 = 0.0f, c1 = 0.0f;
    for (int tt = half; tt < TT; tt += 2) {
        const float* p = obase + (size_t)tt * 64;
        const float v0 = p[j];
        const float v1 = p[j + 32];
        float v = v0 * aw0 + v1 * aw1;
        #pragma unroll
        for (int o = 16; o; o >>= 1) v += __shfl_xor_sync(0xffffffffu, v, o);
        const float mn = fmaxf(m, v);
        const float sc = __expf(m - mn);
        const float e  = __expf(v - mn);
        Z  = Z * sc + e;
        c0 = c0 * sc + e * v0;
        c1 = c1 * sc + e * v1;
        m = mn;
    }
    if (j == 0) sm[warp] = m;
    __syncthreads();

    const float M  = fmaxf(sm[warp & ~1], sm[warp | 1]);
    const float sc = __expf(m - M);
    if (j == 0) szs[warp] = Z * sc;
    sctx[warp][j]      = c0 * sc;
    sctx[warp][j + 32] = c1 * sc;
    __syncthreads();

    if ((warp & 1) == 0) {
        const float Zt = szs[warp] + szs[warp + 1];
        const float C0 = sctx[warp][j]      + sctx[warp + 1][j];
        const float C1 = sctx[warp][j + 32] + sctx[warp + 1][j + 32];
        float v = C0 * sfw[j] + C1 * sfw[j + 32];
        #pragma unroll
        for (int o = 16; o; o >>= 1) v += __shfl_xor_sync(0xffffffffu, v, o);
        if (j == 0) {
            y[ba] = frcp(1.0f + __expf(-(__fdividef(v, Zt) + fc_b[0])));
        }
    }
}

extern "C" void kernel_launch(void* const* d_in, const int* in_sizes, int n_in,
                              void* d_out, int out_size) {
    const float* x       = (const float*)d_in[0];
    const float* w_ih_l0 = (const float*)d_in[1];
    const float* w_hh_l0 = (const float*)d_in[2];
    const float* b_ih_l0 = (const float*)d_in[3];
    const float* b_hh_l0 = (const float*)d_in[4];
    const float* w_ih_l1 = (const float*)d_in[5];
    const float* w_hh_l1 = (const float*)d_in[6];
    const float* b_ih_l1 = (const float*)d_in[7];
    const float* b_hh_l1 = (const float*)d_in[8];
    const float* attn_w  = (const float*)d_in[9];
    // d_in[10] = attn_b (cancels in softmax)
    const float* fc_w    = (const float*)d_in[11];
    const float* fc_b    = (const float*)d_in[12];
    float* y = (float*)d_out;

    gru_l0         <<<dim3(BB / 4, 2), 128>>>(x, w_ih_l0, w_hh_l0, b_ih_l0, b_hh_l0);
    gru_l1_xg      <<<(BB * 2 * 2) / 4, 128>>>(w_ih_l1, b_ih_l1);
    gru_l1_rec_attn<<<BB / 4, 256>>>(w_hh_l1, b_hh_l1, attn_w, fc_w, fc_b, y);
}

// round 14
// speedup vs baseline: 2.3017x; 1.1112x over previous
#include <cuda_runtime.h>
#include <cuda_fp16.h>
#include <math.h>

#define BB 1024
#define TT 512
#define II 4
#define HH 32
#define GG 96   // 3*H

typedef unsigned long long u64;

// Scratch sequence buffers (allocation-free rule: __device__ globals).
__device__ __half g_h1 [(size_t)BB * TT * 2 * HH];   // layer0 out (fp16)
__device__ u64    g_xg [(size_t)2 * BB * TT * HH];   // layer1 gates packed (r,z,n,pad)
__device__ float  g_out[(size_t)BB * TT * 2 * HH];   // layer1 out (fp32)

__device__ __forceinline__ u64 fma2(u64 a, u64 b, u64 c) {
    u64 d;
    asm("fma.rn.f32x2 %0, %1, %2, %3;" : "=l"(d) : "l"(a), "l"(b), "l"(c));
    return d;
}
__device__ __forceinline__ float sum2(u64 v) {
    float lo, hi;
    asm("mov.b64 {%0, %1}, %2;" : "=f"(lo), "=f"(hi) : "l"(v));
    return lo + hi;
}
__device__ __forceinline__ u64 pack2(float lo, float hi) {
    u64 d;
    asm("mov.b64 %0, {%1, %2};" : "=l"(d) : "f"(lo), "f"(hi));
    return d;
}
__device__ __forceinline__ float frcp(float x) {
    float y;
    asm("rcp.approx.f32 %0, %1;" : "=f"(y) : "f"(x));
    return y;
}
// HW tanh: single MUFU op, lat ~16 (vs ~48-cycle exp/rcp ladder)
__device__ __forceinline__ float ftanh(float x) {
    float y;
    asm("tanh.approx.f32 %0, %1;" : "=f"(y) : "f"(x));
    return y;
}
// sigmoid(x) = 0.5*tanh(0.5x) + 0.5  -> 1 FMUL-equiv + 1 MUFU + 1 FFMA
__device__ __forceinline__ float fsig(float x) {
    return fmaf(0.5f, ftanh(0.5f * x), 0.5f);
}
__device__ __forceinline__ __half2 u64_to_h2(u64 v) {
    float lo, hi;
    asm("mov.b64 {%0, %1}, %2;" : "=f"(lo), "=f"(hi) : "l"(v));
    return __floats2half2_rn(lo, hi);
}
__device__ __forceinline__ float h2sum(__half2 v) {
    return __low2float(v) + __high2float(v);
}
#define H2(u) (*(const __half2*)&(u))

// ---------------------------------------------------------------------------
// Layer 0: one warp per (b, dir). HFMA2 MACs, prefetch depth 2, HW tanh.
// grid: (B/4, 2), block 128.
// ---------------------------------------------------------------------------
__global__ void __launch_bounds__(128) gru_l0(
    const float* __restrict__ x,      // [B,T,4]
    const float* __restrict__ w_ih,   // [2,96,4]
    const float* __restrict__ w_hh,   // [2,96,32]
    const float* __restrict__ b_ih,   // [2,96]
    const float* __restrict__ b_hh)   // [2,96]
{
    __shared__ __align__(16) __half sh[4][2][32];

    const int warp = threadIdx.x >> 5;
    const int j    = threadIdx.x & 31;
    const int dir  = blockIdx.y;
    const int b    = blockIdx.x * 4 + warp;

    const u64* w64 = (const u64*)w_hh;
    __half2 wr[16], wz[16], wn[16];
    {
        const int rb = (dir * GG + j) * 16;
        const int zb = (dir * GG + 32 + j) * 16;
        const int nb = (dir * GG + 64 + j) * 16;
        #pragma unroll
        for (int m = 0; m < 16; m++) {
            wr[m] = u64_to_h2(w64[rb + m]);
            wz[m] = u64_to_h2(w64[zb + m]);
            wn[m] = u64_to_h2(w64[nb + m]);
        }
    }
    const u64* wi64 = (const u64*)w_ih;
    const u64 wrA = wi64[(dir * GG + j) * 2],      wrB = wi64[(dir * GG + j) * 2 + 1];
    const u64 wzA = wi64[(dir * GG + 32 + j) * 2], wzB = wi64[(dir * GG + 32 + j) * 2 + 1];
    const u64 wnA = wi64[(dir * GG + 64 + j) * 2], wnB = wi64[(dir * GG + 64 + j) * 2 + 1];

    const u64 br2 = pack2(b_ih[dir * GG + j]      + b_hh[dir * GG + j],      0.0f);
    const u64 bz2 = pack2(b_ih[dir * GG + 32 + j] + b_hh[dir * GG + 32 + j], 0.0f);
    const u64 bx2 = pack2(b_ih[dir * GG + 64 + j], 0.0f);
    const float bhn = b_hh[dir * GG + 64 + j];

    float h = 0.0f;
    const int tstep = dir ? -1 : 1;
    int t = dir ? (TT - 1) : 0;

    const ulonglong2* xb2 = (const ulonglong2*)(x + (size_t)b * TT * II);
    __half* ob = g_h1 + (size_t)b * TT * 2 * HH + dir * HH + j;

    ulonglong2 xq0 = xb2[t];
    ulonglong2 xq1 = xb2[t + tstep];

    for (int s = 0; s < TT; ++s, t += tstep) {
        int tp = t + 2 * tstep;
        tp = (tp < 0) ? 0 : ((tp >= TT) ? (TT - 1) : tp);
        const ulonglong2 xq2 = xb2[tp];

        const int par = s & 1;
        sh[warp][par][j] = __float2half(h);
        __syncwarp();

        const u64 rin2 = fma2(wrA, xq0.x, fma2(wrB, xq0.y, br2));
        const u64 zin2 = fma2(wzA, xq0.x, fma2(wzB, xq0.y, bz2));
        const u64 xin2 = fma2(wnA, xq0.x, fma2(wnB, xq0.y, bx2));

        __half2 r0, r1, z0, z1, n0, n1;
        r0 = r1 = z0 = z1 = n0 = n1 = __floats2half2_rn(0.0f, 0.0f);
        const uint4* hv = (const uint4*)sh[warp][par];
        #pragma unroll
        for (int q = 0; q < 4; q++) {
            const uint4 u = hv[q];
            r0 = __hfma2(wr[4 * q],     H2(u.x), r0);
            z0 = __hfma2(wz[4 * q],     H2(u.x), z0);
            n0 = __hfma2(wn[4 * q],     H2(u.x), n0);
            r1 = __hfma2(wr[4 * q + 1], H2(u.y), r1);
            z1 = __hfma2(wz[4 * q + 1], H2(u.y), z1);
            n1 = __hfma2(wn[4 * q + 1], H2(u.y), n1);
            r0 = __hfma2(wr[4 * q + 2], H2(u.z), r0);
            z0 = __hfma2(wz[4 * q + 2], H2(u.z), z0);
            n0 = __hfma2(wn[4 * q + 2], H2(u.z), n0);
            r1 = __hfma2(wr[4 * q + 3], H2(u.w), r1);
            z1 = __hfma2(wz[4 * q + 3], H2(u.w), z1);
            n1 = __hfma2(wn[4 * q + 3], H2(u.w), n1);
        }

        const float r = fsig(sum2(rin2) + h2sum(__hadd2(r0, r1)));
        const float z = fsig(sum2(zin2) + h2sum(__hadd2(z0, z1)));
        const float n = ftanh(sum2(xin2) + r * (bhn + h2sum(__hadd2(n0, n1))));
        h = n + z * (h - n);

        ob[(size_t)t * 2 * HH] = __float2half(h);
        xq0 = xq1; xq1 = xq2;
    }
}

// ---------------------------------------------------------------------------
// Layer 1 input projection, packed u64 gate output. block 128, grid 1024.
// ---------------------------------------------------------------------------
__global__ void __launch_bounds__(128) gru_l1_xg(
    const float* __restrict__ w_ih,   // [2,96,64]
    const float* __restrict__ b_ih)   // [2,96]
{
    __shared__ __align__(16) unsigned int sx[4][2][2][32];

    const int w = threadIdx.x >> 5;
    const int j = threadIdx.x & 31;

    const int task  = blockIdx.x * 4 + w;   // (b*2 + dir)*2 + chunkhalf
    const int chalf = task & 1;
    const int bd    = task >> 1;
    const int dir   = bd & 1;
    const int b     = bd >> 1;

    const u64* w64 = (const u64*)w_ih;
    __half2 wgr[32], wgz[32], wgn[32];
    {
        const int rb = (dir * GG + j) * 32;
        const int zb = (dir * GG + 32 + j) * 32;
        const int nb = (dir * GG + 64 + j) * 32;
        #pragma unroll
        for (int m = 0; m < 32; m++) {
            wgr[m] = u64_to_h2(w64[rb + m]);
            wgz[m] = u64_to_h2(w64[zb + m]);
            wgn[m] = u64_to_h2(w64[nb + m]);
        }
    }
    const float br = b_ih[dir * GG + j];
    const float bz = b_ih[dir * GG + 32 + j];
    const float bn = b_ih[dir * GG + 64 + j];

    const unsigned int* ib = (const unsigned int*)g_h1 + (size_t)b * TT * 32;
    u64* xo = g_xg + ((size_t)(dir * BB + b) * TT) * 32 + j;

    const int t0 = chalf * (TT / 2);
    unsigned int a0 = ib[(size_t)t0 * 32 + j];
    unsigned int a1 = ib[(size_t)(t0 + 1) * 32 + j];

    for (int s = 0; s < TT / 4; ++s) {
        const int t  = t0 + 2 * s;
        const int tn = (s == TT / 4 - 1) ? t : (t + 2);
        const unsigned int p0 = ib[(size_t)tn * 32 + j];
        const unsigned int p1 = ib[(size_t)(tn + 1) * 32 + j];

        const int par = s & 1;
        sx[w][par][0][j] = a0;
        sx[w][par][1][j] = a1;
        __syncwarp();

        __half2 R0, R1, Z0, Z1, N0, N1;
        __half2 R2, R3, Z2, Z3, N2, N3;
        R0 = R1 = Z0 = Z1 = N0 = N1 = __floats2half2_rn(0.0f, 0.0f);
        R2 = R3 = Z2 = Z3 = N2 = N3 = __floats2half2_rn(0.0f, 0.0f);

        const uint4* r0p = (const uint4*)&sx[w][par][0][0];
        const uint4* r1p = (const uint4*)&sx[w][par][1][0];
        #pragma unroll
        for (int q = 0; q < 8; q++) {
            const uint4 u = r0p[q];
            const uint4 v = r1p[q];
            R0 = __hfma2(wgr[4 * q],     H2(u.x), R0);
            Z0 = __hfma2(wgz[4 * q],     H2(u.x), Z0);
            N0 = __hfma2(wgn[4 * q],     H2(u.x), N0);
            R1 = __hfma2(wgr[4 * q + 1], H2(u.y), R1);
            Z1 = __hfma2(wgz[4 * q + 1], H2(u.y), Z1);
            N1 = __hfma2(wgn[4 * q + 1], H2(u.y), N1);
            R0 = __hfma2(wgr[4 * q + 2], H2(u.z), R0);
            Z0 = __hfma2(wgz[4 * q + 2], H2(u.z), Z0);
            N0 = __hfma2(wgn[4 * q + 2], H2(u.z), N0);
            R1 = __hfma2(wgr[4 * q + 3], H2(u.w), R1);
            Z1 = __hfma2(wgz[4 * q + 3], H2(u.w), Z1);
            N1 = __hfma2(wgn[4 * q + 3], H2(u.w), N1);

            R2 = __hfma2(wgr[4 * q],     H2(v.x), R2);
            Z2 = __hfma2(wgz[4 * q],     H2(v.x), Z2);
            N2 = __hfma2(wgn[4 * q],     H2(v.x), N2);
            R3 = __hfma2(wgr[4 * q + 1], H2(v.y), R3);
            Z3 = __hfma2(wgz[4 * q + 1], H2(v.y), Z3);
            N3 = __hfma2(wgn[4 * q + 1], H2(v.y), N3);
            R2 = __hfma2(wgr[4 * q + 2], H2(v.z), R2);
            Z2 = __hfma2(wgz[4 * q + 2], H2(v.z), Z2);
            N2 = __hfma2(wgn[4 * q + 2], H2(v.z), N2);
            R3 = __hfma2(wgr[4 * q + 3], H2(v.w), R3);
            Z3 = __hfma2(wgz[4 * q + 3], H2(v.w), Z3);
            N3 = __hfma2(wgn[4 * q + 3], H2(v.w), N3);
        }

        {
            const float rv = br + h2sum(__hadd2(R0, R1));
            const float zv = bz + h2sum(__hadd2(Z0, Z1));
            const float nv = bn + h2sum(__hadd2(N0, N1));
            const __half2 lo = __floats2half2_rn(rv, zv);
            const __half2 hi = __floats2half2_rn(nv, 0.0f);
            u64 pk;
            asm("mov.b64 %0, {%1, %2};" : "=l"(pk)
                : "r"(*(const unsigned int*)&lo), "r"(*(const unsigned int*)&hi));
            xo[(size_t)t * 32] = pk;
        }
        {
            const float rv = br + h2sum(__hadd2(R2, R3));
            const float zv = bz + h2sum(__hadd2(Z2, Z3));
            const float nv = bn + h2sum(__hadd2(N2, N3));
            const __half2 lo = __floats2half2_rn(rv, zv);
            const __half2 hi = __floats2half2_rn(nv, 0.0f);
            u64 pk;
            asm("mov.b64 %0, {%1, %2};" : "=l"(pk)
                : "r"(*(const unsigned int*)&lo), "r"(*(const unsigned int*)&hi));
            xo[(size_t)(t + 1) * 32] = pk;
        }
        a0 = p0; a1 = p1;
    }
}

// ---------------------------------------------------------------------------
// Layer 1 recurrence: single u64 gate load/step, prefetch depth 3, HW tanh.
// grid (B/4, 2), block 128.
// ---------------------------------------------------------------------------
__global__ void __launch_bounds__(128) gru_l1_rec(
    const float* __restrict__ w_hh,   // [2,96,32]
    const float* __restrict__ b_hh)   // [2,96]
{
    __shared__ __align__(16) __half sh[4][2][32];

    const int warp = threadIdx.x >> 5;
    const int j    = threadIdx.x & 31;
    const int dir  = blockIdx.y;
    const int b    = blockIdx.x * 4 + warp;

    const u64* w64 = (const u64*)w_hh;
    __half2 wr[16], wz[16], wn[16];
    {
        const int rb = (dir * GG + j) * 16;
        const int zb = (dir * GG + 32 + j) * 16;
        const int nb = (dir * GG + 64 + j) * 16;
        #pragma unroll
        for (int m = 0; m < 16; m++) {
            wr[m] = u64_to_h2(w64[rb + m]);
            wz[m] = u64_to_h2(w64[zb + m]);
            wn[m] = u64_to_h2(w64[nb + m]);
        }
    }
    const float brh = b_hh[dir * GG + j];
    const float bzh = b_hh[dir * GG + 32 + j];
    const float bhn = b_hh[dir * GG + 64 + j];

    float h = 0.0f;
    const int tstep = dir ? -1 : 1;
    int t = dir ? (TT - 1) : 0;

    const u64* xgb = g_xg + ((size_t)(dir * BB + b) * TT) * 32 + j;
    float* ob = g_out + (size_t)b * TT * 2 * HH + dir * HH + j;

    u64 q0 = xgb[(size_t)t * 32];
    u64 q1 = xgb[(size_t)(t + tstep) * 32];
    u64 q2 = xgb[(size_t)(t + 2 * tstep) * 32];

    for (int s = 0; s < TT; ++s, t += tstep) {
        int tp = t + 3 * tstep;
        tp = (tp < 0) ? 0 : ((tp >= TT) ? (TT - 1) : tp);
        const u64 q3 = xgb[(size_t)tp * 32];

        const int par = s & 1;
        sh[warp][par][j] = __float2half(h);
        __syncwarp();

        unsigned int lo_u, hi_u;
        asm("mov.b64 {%0, %1}, %2;" : "=r"(lo_u), "=r"(hi_u) : "l"(q0));
        const __half2 lo = H2(lo_u);
        const __half2 hi = H2(hi_u);
        const float xr = __low2float(lo);
        const float xz = __high2float(lo);
        const float xn = __low2float(hi);

        __half2 r0, r1, z0, z1, n0, n1;
        r0 = r1 = z0 = z1 = n0 = n1 = __floats2half2_rn(0.0f, 0.0f);
        const uint4* hv = (const uint4*)sh[warp][par];
        #pragma unroll
        for (int q = 0; q < 4; q++) {
            const uint4 u = hv[q];
            r0 = __hfma2(wr[4 * q],     H2(u.x), r0);
            z0 = __hfma2(wz[4 * q],     H2(u.x), z0);
            n0 = __hfma2(wn[4 * q],     H2(u.x), n0);
            r1 = __hfma2(wr[4 * q + 1], H2(u.y), r1);
            z1 = __hfma2(wz[4 * q + 1], H2(u.y), z1);
            n1 = __hfma2(wn[4 * q + 1], H2(u.y), n1);
            r0 = __hfma2(wr[4 * q + 2], H2(u.z), r0);
            z0 = __hfma2(wz[4 * q + 2], H2(u.z), z0);
            n0 = __hfma2(wn[4 * q + 2], H2(u.z), n0);
            r1 = __hfma2(wr[4 * q + 3], H2(u.w), r1);
            z1 = __hfma2(wz[4 * q + 3], H2(u.w), z1);
            n1 = __hfma2(wn[4 * q + 3], H2(u.w), n1);
        }

        const float r = fsig(xr + brh + h2sum(__hadd2(r0, r1)));
        const float z = fsig(xz + bzh + h2sum(__hadd2(z0, z1)));
        const float n = ftanh(xn + r * (bhn + h2sum(__hadd2(n0, n1))));
        h = n + z * (h - n);

        ob[(size_t)t * 2 * HH] = h;
        q0 = q1; q1 = q2; q2 = q3;
    }
}

// ---------------------------------------------------------------------------
// Epilogue: single-pass online-softmax attention pooling + sigmoid FC.
// ---------------------------------------------------------------------------
__global__ void __launch_bounds__(256) attn_fc_kernel(
    const float* __restrict__ attn_w,  // [1,64]
    const float* __restrict__ fc_w,    // [1,64]
    const float* __restrict__ fc_b,    // [1]
    float* __restrict__ y)             // [B,1]
{
    __shared__ float saw[64], sfw[64];
    __shared__ float sm[8], sz[8];
    __shared__ float sctx[8][64];

    const int b    = blockIdx.x;
    const int tid  = threadIdx.x;
    const int warp = tid >> 5;
    const int lane = tid & 31;

    if (tid < 64) {
        saw[tid] = attn_w[tid];
        sfw[tid] = fc_w[tid];
    }
    __syncthreads();

    const float aw0 = saw[lane], aw1 = saw[lane + 32];
    const float* ob = g_out + (size_t)b * TT * 64;

    float m = -INFINITY, Z = 0.0f, c0 = 0.0f, c1 = 0.0f;
    for (int t = warp; t < TT; t += 8) {
        const float* p = ob + (size_t)t * 64;
        const float q0 = p[lane];
        const float q1 = p[lane + 32];
        float v = q0 * aw0 + q1 * aw1;
        #pragma unroll
        for (int o = 16; o; o >>= 1) v += __shfl_xor_sync(0xffffffffu, v, o);
        const float mn = fmaxf(m, v);
        const float sc = __expf(m - mn);
        const float e  = __expf(v - mn);
        Z  = Z * sc + e;
        c0 = c0 * sc + e * q0;
        c1 = c1 * sc + e * q1;
        m = mn;
    }
    if (lane == 0) sm[warp] = m;
    __syncthreads();

    float M = sm[0];
    #pragma unroll
    for (int w = 1; w < 8; w++) M = fmaxf(M, sm[w]);
    const float sc = __expf(m - M);
    if (lane == 0) sz[warp] = Z * sc;
    sctx[warp][lane]      = c0 * sc;
    sctx[warp][lane + 32] = c1 * sc;
    __syncthreads();

    if (tid < 32) {
        float Zt = 0.0f, C0 = 0.0f, C1 = 0.0f;
        #pragma unroll
        for (int w = 0; w < 8; w++) {
            Zt += sz[w];
            C0 += sctx[w][lane];
            C1 += sctx[w][lane + 32];
        }
        float v = C0 * sfw[lane] + C1 * sfw[lane + 32];
        #pragma unroll
        for (int o = 16; o; o >>= 1) v += __shfl_xor_sync(0xffffffffu, v, o);
        if (lane == 0) {
            y[b] = fmaf(0.5f, ftanh(0.5f * (__fdividef(v, Zt) + fc_b[0])), 0.5f);
        }
    }
}

extern "C" void kernel_launch(void* const* d_in, const int* in_sizes, int n_in,
                              void* d_out, int out_size) {
    const float* x       = (const float*)d_in[0];
    const float* w_ih_l0 = (const float*)d_in[1];
    const float* w_hh_l0 = (const float*)d_in[2];
    const float* b_ih_l0 = (const float*)d_in[3];
    const float* b_hh_l0 = (const float*)d_in[4];
    const float* w_ih_l1 = (const float*)d_in[5];
    const float* w_hh_l1 = (const float*)d_in[6];
    const float* b_ih_l1 = (const float*)d_in[7];
    const float* b_hh_l1 = (const float*)d_in[8];
    const float* attn_w  = (const float*)d_in[9];
    // d_in[10] = attn_b (cancels in softmax)
    const float* fc_w    = (const float*)d_in[11];
    const float* fc_b    = (const float*)d_in[12];
    float* y = (float*)d_out;

    gru_l0    <<<dim3(BB / 4, 2), 128>>>(x, w_ih_l0, w_hh_l0, b_ih_l0, b_hh_l0);
    gru_l1_xg <<<(BB * 2 * 2) / 4, 128>>>(w_ih_l1, b_ih_l1);
    gru_l1_rec<<<dim3(BB / 4, 2), 128>>>(w_hh_l1, b_hh_l1);
    attn_fc_kernel<<<BB, 256>>>(attn_w, fc_w, fc_b, y);
}